// round 8
// baseline (speedup 1.0000x reference)
#include <cuda_runtime.h>
#include <cuda_fp16.h>
#include <cstdint>

#define NODES_CAP 50000
#define BUCKET_CAP 64

// Scratch (no allocations allowed -> __device__ globals)
__device__ float g_neigh[(size_t)NODES_CAP * 128];   // pre-normalized h_neigh
__device__ uint2 g_feat16[(size_t)NODES_CAP * 32];   // feat packed as half2 x2 per uint2
__device__ int g_cnt[NODES_CAP];
__device__ unsigned long long g_bucket[(size_t)NODES_CAP * BUCKET_CAP];  // (w<<32)|src
__device__ float g_whi[256 * 128];   // combined W, k-major [k][n], tf32 hi
__device__ float g_wlo[256 * 128];   // tf32 lo residual
__device__ float g_colsum[128];
__device__ float g_colsq[128];
__device__ float g_scale[128];
__device__ float g_shift[128];

__device__ __forceinline__ unsigned tf32_rna(float a) {
    unsigned r;
    asm("cvt.rna.tf32.f32 %0, %1;" : "=r"(r) : "f"(a));
    return r;
}

__device__ __forceinline__ unsigned h2_to_u32(__half2 h) {
    union { __half2 h; unsigned u; } cv;
    cv.h = h;
    return cv.u;
}

__device__ __forceinline__ float2 u32_to_f2(unsigned u) {
    union { unsigned u; __half2 h; } cv;
    cv.u = u;
    return __half22float2(cv.h);
}

// ---------------------------------------------------------------------------
// Zero small scratch
// ---------------------------------------------------------------------------
__global__ void zero_scratch(int N) {
    int i = blockIdx.x * blockDim.x + threadIdx.x;
    if (i < N) g_cnt[i] = 0;
    if (i < 128) { g_colsum[i] = 0.f; g_colsq[i] = 0.f; }
}

// ---------------------------------------------------------------------------
// Convert feat to packed fp16 (halves gather traffic in node_aggregate)
// ---------------------------------------------------------------------------
__global__ __launch_bounds__(256) void feat_to_half(const float* __restrict__ feat, long tot4) {
    long i = (long)blockIdx.x * blockDim.x + threadIdx.x;
    if (i >= tot4) return;
    float4 v = reinterpret_cast<const float4*>(feat)[i];
    uint2 p;
    p.x = h2_to_u32(__floats2half2_rn(v.x, v.y));
    p.y = h2_to_u32(__floats2half2_rn(v.z, v.w));
    g_feat16[i] = p;
}

// ---------------------------------------------------------------------------
// Pre-split combined weight matrix into tf32 hi/lo, transposed to k-major.
// B[k][n] = (k<128) ? Ws[n][k] : Wn[n][k-128]
// ---------------------------------------------------------------------------
__global__ void split_w(const float* __restrict__ Wn, const float* __restrict__ Ws) {
    int i = blockIdx.x * blockDim.x + threadIdx.x;
    if (i >= 256 * 128) return;
    int k = i >> 7, n = i & 127;
    float v = (k < 128) ? Ws[n * 128 + k] : Wn[n * 128 + (k - 128)];
    unsigned hib = tf32_rna(v);
    float hif = __uint_as_float(hib);
    float lof = v - hif;
    g_whi[i] = hif;
    g_wlo[i] = __uint_as_float(tf32_rna(lof));
}

// ---------------------------------------------------------------------------
// Phase A: bin edges into per-dst buckets. One thread per edge.
// ---------------------------------------------------------------------------
__global__ __launch_bounds__(256) void edge_bin(
    const int* __restrict__ src, const int* __restrict__ dst,
    const float* __restrict__ ew, int E)
{
    int e = blockIdx.x * blockDim.x + threadIdx.x;
    if (e >= E) return;
    int d = __ldg(dst + e);
    int s = __ldg(src + e);
    unsigned int w = __float_as_uint(__ldg(ew + e));
    int pos = atomicAdd(g_cnt + d, 1);
    if (pos < BUCKET_CAP)
        g_bucket[(long)d * BUCKET_CAP + pos] =
            ((unsigned long long)w << 32) | (unsigned int)s;
}

// ---------------------------------------------------------------------------
// Phase B: one warp per dst node. fp16 gather (half traffic), fp32 accumulate,
// normalize by (sum_w + eps), write fp32 g_neigh once.
// ---------------------------------------------------------------------------
__global__ __launch_bounds__(256) void node_aggregate(int N)
{
    int warp = (blockIdx.x * blockDim.x + threadIdx.x) >> 5;
    int lane = threadIdx.x & 31;
    if (warp >= N) return;
    int cnt = g_cnt[warp];
    if (cnt > BUCKET_CAP) cnt = BUCKET_CAP;
    const unsigned long long* bk = g_bucket + (long)warp * BUCKET_CAP;

    float4 acc = make_float4(0.f, 0.f, 0.f, 0.f);
    float wsum = 0.f;
    int e = 0;
    for (; e + 1 < cnt; e += 2) {
        unsigned long long p0 = bk[e];
        unsigned long long p1 = bk[e + 1];
        int s0 = (int)(unsigned int)p0;
        int s1 = (int)(unsigned int)p1;
        float w0 = __uint_as_float((unsigned int)(p0 >> 32));
        float w1 = __uint_as_float((unsigned int)(p1 >> 32));
        uint2 q0 = g_feat16[(long)s0 * 32 + lane];
        uint2 q1 = g_feat16[(long)s1 * 32 + lane];
        float2 a0 = u32_to_f2(q0.x);
        float2 b0 = u32_to_f2(q0.y);
        float2 a1 = u32_to_f2(q1.x);
        float2 b1 = u32_to_f2(q1.y);
        acc.x = fmaf(w0, a0.x, acc.x); acc.y = fmaf(w0, a0.y, acc.y);
        acc.z = fmaf(w0, b0.x, acc.z); acc.w = fmaf(w0, b0.y, acc.w);
        acc.x = fmaf(w1, a1.x, acc.x); acc.y = fmaf(w1, a1.y, acc.y);
        acc.z = fmaf(w1, b1.x, acc.z); acc.w = fmaf(w1, b1.y, acc.w);
        wsum += w0 + w1;
    }
    if (e < cnt) {
        unsigned long long p0 = bk[e];
        int s0 = (int)(unsigned int)p0;
        float w0 = __uint_as_float((unsigned int)(p0 >> 32));
        uint2 q0 = g_feat16[(long)s0 * 32 + lane];
        float2 a0 = u32_to_f2(q0.x);
        float2 b0 = u32_to_f2(q0.y);
        acc.x = fmaf(w0, a0.x, acc.x); acc.y = fmaf(w0, a0.y, acc.y);
        acc.z = fmaf(w0, b0.x, acc.z); acc.w = fmaf(w0, b0.y, acc.w);
        wsum += w0;
    }
    float inv = 1.f / (wsum + 1e-8f);
    acc.x *= inv; acc.y *= inv; acc.z *= inv; acc.w *= inv;
    *reinterpret_cast<float4*>(g_neigh + (long)warp * 128 + lane * 4) = acc;
}

// ---------------------------------------------------------------------------
// Tensor-core GEMM (3xTF32): out = relu([feat|neigh] @ B + b_self + bias)
// Block: 64 rows x 128 cols, 128 threads (4 warps). Warp w owns cols [w*32,+32).
// Epilogue also accumulates BN column stats (sum, sumsq) via smem + global atomics.
// ---------------------------------------------------------------------------
#define APITCH 36
#define BPITCH 136

__global__ __launch_bounds__(128) void gemm_tc(
    const float* __restrict__ feat,
    const float* __restrict__ b_self,
    const float* __restrict__ bias,
    float* __restrict__ out, int N)
{
    __shared__ __align__(16) float sA[64][APITCH];     // 9216 B
    __shared__ __align__(16) float sBhi[32][BPITCH];   // 17408 B
    __shared__ __align__(16) float sBlo[32][BPITCH];   // 17408 B
    __shared__ float sS[128];
    __shared__ float sQ[128];

    const int tid = threadIdx.x;
    const int warp = tid >> 5;
    const int lane = tid & 31;
    const int row0 = blockIdx.x * 64;
    const int n0w = warp * 32;
    const int lq = lane >> 2;   // 0..7
    const int lr = lane & 3;    // 0..3

    if (tid < 128) { sS[tid] = 0.f; sQ[tid] = 0.f; }

    float C[4][4][4];
#pragma unroll
    for (int mt = 0; mt < 4; mt++)
#pragma unroll
        for (int nt = 0; nt < 4; nt++)
#pragma unroll
            for (int j = 0; j < 4; j++) C[mt][nt][j] = 0.f;

    for (int kt = 0; kt < 8; kt++) {
        __syncthreads();
        // Load A tile: 64 rows x 32 k (feat for kt<4, neigh for kt>=4)
        const float* Asrc = (kt < 4) ? feat : g_neigh;
        int kofs = (kt & 3) * 32;
#pragma unroll
        for (int i = 0; i < 4; i++) {
            int idx = tid + i * 128;          // 0..511 float4s
            int r = idx >> 3;
            int c4 = idx & 7;
            float4 v = make_float4(0.f, 0.f, 0.f, 0.f);
            int gr = row0 + r;
            if (gr < N)
                v = *reinterpret_cast<const float4*>(Asrc + (long)gr * 128 + kofs + c4 * 4);
            *reinterpret_cast<float4*>(&sA[r][c4 * 4]) = v;
        }
        // Load B tiles: rows kt*32 .. kt*32+31, 128 cols, hi and lo
        int kb = kt * 32;
#pragma unroll
        for (int i = 0; i < 8; i++) {
            int idx = tid + i * 128;          // 0..1023 float4s
            int kr = idx >> 5;
            int c4 = idx & 31;
            float4 vh = *reinterpret_cast<const float4*>(g_whi + (long)(kb + kr) * 128 + c4 * 4);
            float4 vl = *reinterpret_cast<const float4*>(g_wlo + (long)(kb + kr) * 128 + c4 * 4);
            *reinterpret_cast<float4*>(&sBhi[kr][c4 * 4]) = vh;
            *reinterpret_cast<float4*>(&sBlo[kr][c4 * 4]) = vl;
        }
        __syncthreads();

#pragma unroll
        for (int k8 = 0; k8 < 4; k8++) {
            int kk = k8 * 8;
            unsigned ahi[4][4], alo[4][4];
#pragma unroll
            for (int mt = 0; mt < 4; mt++) {
                int r = mt * 16 + lq;
                float a0 = sA[r][kk + lr];
                float a1 = sA[r + 8][kk + lr];
                float a2 = sA[r][kk + lr + 4];
                float a3 = sA[r + 8][kk + lr + 4];
                ahi[mt][0] = tf32_rna(a0);
                ahi[mt][1] = tf32_rna(a1);
                ahi[mt][2] = tf32_rna(a2);
                ahi[mt][3] = tf32_rna(a3);
                alo[mt][0] = tf32_rna(a0 - __uint_as_float(ahi[mt][0]));
                alo[mt][1] = tf32_rna(a1 - __uint_as_float(ahi[mt][1]));
                alo[mt][2] = tf32_rna(a2 - __uint_as_float(ahi[mt][2]));
                alo[mt][3] = tf32_rna(a3 - __uint_as_float(ahi[mt][3]));
            }
#pragma unroll
            for (int nt = 0; nt < 4; nt++) {
                int n = n0w + nt * 8 + lq;
                unsigned bh0 = __float_as_uint(sBhi[kk + lr][n]);
                unsigned bh1 = __float_as_uint(sBhi[kk + lr + 4][n]);
                unsigned bl0 = __float_as_uint(sBlo[kk + lr][n]);
                unsigned bl1 = __float_as_uint(sBlo[kk + lr + 4][n]);
#pragma unroll
                for (int mt = 0; mt < 4; mt++) {
                    float* c = C[mt][nt];
                    asm volatile(
                        "mma.sync.aligned.m16n8k8.row.col.f32.tf32.tf32.f32 "
                        "{%0,%1,%2,%3}, {%4,%5,%6,%7}, {%8,%9}, {%0,%1,%2,%3};"
                        : "+f"(c[0]), "+f"(c[1]), "+f"(c[2]), "+f"(c[3])
                        : "r"(ahi[mt][0]), "r"(ahi[mt][1]), "r"(ahi[mt][2]), "r"(ahi[mt][3]),
                          "r"(bh0), "r"(bh1));
                    asm volatile(
                        "mma.sync.aligned.m16n8k8.row.col.f32.tf32.tf32.f32 "
                        "{%0,%1,%2,%3}, {%4,%5,%6,%7}, {%8,%9}, {%0,%1,%2,%3};"
                        : "+f"(c[0]), "+f"(c[1]), "+f"(c[2]), "+f"(c[3])
                        : "r"(ahi[mt][0]), "r"(ahi[mt][1]), "r"(ahi[mt][2]), "r"(ahi[mt][3]),
                          "r"(bl0), "r"(bl1));
                    asm volatile(
                        "mma.sync.aligned.m16n8k8.row.col.f32.tf32.tf32.f32 "
                        "{%0,%1,%2,%3}, {%4,%5,%6,%7}, {%8,%9}, {%0,%1,%2,%3};"
                        : "+f"(c[0]), "+f"(c[1]), "+f"(c[2]), "+f"(c[3])
                        : "r"(alo[mt][0]), "r"(alo[mt][1]), "r"(alo[mt][2]), "r"(alo[mt][3]),
                          "r"(bh0), "r"(bh1));
                }
            }
        }
    }

    // Epilogue: bias + ReLU, write, and accumulate BN column stats.
    // C layout: c0:(r=lq, c=lr*2) c1:(r, c+1) c2:(r+8, c) c3:(r+8, c+1)
#pragma unroll
    for (int nt = 0; nt < 4; nt++) {
        int c = n0w + nt * 8 + lr * 2;
        float bc0 = __ldg(b_self + c) + __ldg(bias + c);
        float bc1 = __ldg(b_self + c + 1) + __ldg(bias + c + 1);
        float s0 = 0.f, s1 = 0.f, q0 = 0.f, q1 = 0.f;
#pragma unroll
        for (int mt = 0; mt < 4; mt++) {
            int r = row0 + mt * 16 + lq;
            if (r < N) {
                float v0 = fmaxf(C[mt][nt][0] + bc0, 0.f);
                float v1 = fmaxf(C[mt][nt][1] + bc1, 0.f);
                *reinterpret_cast<float2*>(out + (long)r * 128 + c) = make_float2(v0, v1);
                s0 += v0; s1 += v1;
                q0 = fmaf(v0, v0, q0); q1 = fmaf(v1, v1, q1);
            }
            if (r + 8 < N) {
                float v2 = fmaxf(C[mt][nt][2] + bc0, 0.f);
                float v3 = fmaxf(C[mt][nt][3] + bc1, 0.f);
                *reinterpret_cast<float2*>(out + (long)(r + 8) * 128 + c) = make_float2(v2, v3);
                s0 += v2; s1 += v3;
                q0 = fmaf(v2, v2, q0); q1 = fmaf(v3, v3, q1);
            }
        }
        atomicAdd(&sS[c], s0); atomicAdd(&sS[c + 1], s1);
        atomicAdd(&sQ[c], q0); atomicAdd(&sQ[c + 1], q1);
    }
    __syncthreads();
    if (tid < 128) {
        atomicAdd(g_colsum + tid, sS[tid]);
        atomicAdd(g_colsq + tid, sQ[tid]);
    }
}

// ---------------------------------------------------------------------------
// BatchNorm finalize + apply
// ---------------------------------------------------------------------------
__global__ void bn_finalize(const float* __restrict__ gamma,
                            const float* __restrict__ beta, float invN) {
    int c = threadIdx.x;
    float mu = g_colsum[c] * invN;
    float var = g_colsq[c] * invN - mu * mu;
    float sc = rsqrtf(var + 1e-5f) * gamma[c];
    g_scale[c] = sc;
    g_shift[c] = beta[c] - mu * sc;
}

__global__ void bn_apply(float* __restrict__ out, long tot4) {
    long i = (long)blockIdx.x * blockDim.x + threadIdx.x;
    if (i >= tot4) return;
    float4 v = reinterpret_cast<float4*>(out)[i];
    int c0 = (int)(i & 31) * 4;
    v.x = v.x * g_scale[c0 + 0] + g_shift[c0 + 0];
    v.y = v.y * g_scale[c0 + 1] + g_shift[c0 + 1];
    v.z = v.z * g_scale[c0 + 2] + g_shift[c0 + 2];
    v.w = v.w * g_scale[c0 + 3] + g_shift[c0 + 3];
    reinterpret_cast<float4*>(out)[i] = v;
}

// ---------------------------------------------------------------------------
extern "C" void kernel_launch(void* const* d_in, const int* in_sizes, int n_in,
                              void* d_out, int out_size) {
    const float* feat   = (const float*)d_in[0];
    const int*   src    = (const int*)  d_in[1];
    const int*   dst    = (const int*)  d_in[2];
    const float* ew     = (const float*)d_in[3];
    const float* Wn     = (const float*)d_in[4];
    const float* Ws     = (const float*)d_in[5];
    const float* b_self = (const float*)d_in[6];
    const float* bias   = (const float*)d_in[7];
    const float* gamma  = (const float*)d_in[8];
    const float* beta   = (const float*)d_in[9];
    float* out = (float*)d_out;

    int N = in_sizes[0] / 128;
    int E = in_sizes[1];
    long tot4 = (long)N * 32;

    zero_scratch<<<(N + 255) / 256, 256>>>(N);
    feat_to_half<<<(int)((tot4 + 255) / 256), 256>>>(feat, tot4);
    split_w<<<(256 * 128 + 255) / 256, 256>>>(Wn, Ws);
    edge_bin<<<(E + 255) / 256, 256>>>(src, dst, ew, E);
    node_aggregate<<<(N + 7) / 8, 256>>>(N);
    gemm_tc<<<(N + 63) / 64, 128>>>(feat, b_self, bias, out, N);
    bn_finalize<<<1, 128>>>(gamma, beta, 1.0f / (float)N);
    bn_apply<<<(int)((tot4 + 255) / 256), 256>>>(out, tot4);
}

// round 10
// speedup vs baseline: 1.0810x; 1.0810x over previous
#include <cuda_runtime.h>
#include <cuda_fp16.h>
#include <cstdint>

#define NODES_CAP 50000
#define BUCKET_CAP 64

// Scratch (no allocations allowed -> __device__ globals)
__device__ float g_neigh[(size_t)NODES_CAP * 128];   // pre-normalized h_neigh
__device__ uint2 g_feat16[(size_t)NODES_CAP * 32];   // feat packed as half2 x2 per uint2
__device__ int g_cnt[NODES_CAP];
__device__ unsigned long long g_bucket[(size_t)NODES_CAP * BUCKET_CAP];  // (w<<32)|src
__device__ float g_whi[256 * 128];   // combined W, k-major [k][n], tf32 hi
__device__ float g_wlo[256 * 128];   // tf32 lo residual
__device__ float g_colsum[128];
__device__ float g_colsq[128];

__device__ __forceinline__ unsigned tf32_rna(float a) {
    unsigned r;
    asm("cvt.rna.tf32.f32 %0, %1;" : "=r"(r) : "f"(a));
    return r;
}

__device__ __forceinline__ unsigned h2_to_u32(__half2 h) {
    union { __half2 h; unsigned u; } cv;
    cv.h = h;
    return cv.u;
}

__device__ __forceinline__ float2 u32_to_f2(unsigned u) {
    union { unsigned u; __half2 h; } cv;
    cv.u = u;
    return __half22float2(cv.h);
}

// ---------------------------------------------------------------------------
// Prep (fused): zero counters/stats + feat->fp16 convert + weight tf32 split
// ---------------------------------------------------------------------------
__global__ __launch_bounds__(256) void prep(
    const float* __restrict__ feat,
    const float* __restrict__ Wn, const float* __restrict__ Ws,
    int N, long tot4)
{
    long i = (long)blockIdx.x * blockDim.x + threadIdx.x;
    if (i < tot4) {
        float4 v = reinterpret_cast<const float4*>(feat)[i];
        uint2 p;
        p.x = h2_to_u32(__floats2half2_rn(v.x, v.y));
        p.y = h2_to_u32(__floats2half2_rn(v.z, v.w));
        g_feat16[i] = p;
    }
    if (i < N) g_cnt[i] = 0;
    if (i < 128) { g_colsum[i] = 0.f; g_colsq[i] = 0.f; }
    if (i < 256 * 128) {
        int k = (int)i >> 7, n = (int)i & 127;
        float v = (k < 128) ? Ws[n * 128 + k] : Wn[n * 128 + (k - 128)];
        unsigned hib = tf32_rna(v);
        float hif = __uint_as_float(hib);
        g_whi[i] = hif;
        g_wlo[i] = __uint_as_float(tf32_rna(v - hif));
    }
}

// ---------------------------------------------------------------------------
// Phase A: bin edges into per-dst buckets. 4 edges per thread (ILP for the
// atomic latency), vectorized index/weight loads.
// ---------------------------------------------------------------------------
__global__ __launch_bounds__(256) void edge_bin(
    const int* __restrict__ src, const int* __restrict__ dst,
    const float* __restrict__ ew, int E)
{
    int t = blockIdx.x * blockDim.x + threadIdx.x;
    int e0 = t * 4;
    if (e0 >= E) return;
    if (e0 + 3 < E) {
        int4 s4 = *reinterpret_cast<const int4*>(src + e0);
        int4 d4 = *reinterpret_cast<const int4*>(dst + e0);
        float4 w4 = *reinterpret_cast<const float4*>(ew + e0);
        int p0 = atomicAdd(g_cnt + d4.x, 1);
        int p1 = atomicAdd(g_cnt + d4.y, 1);
        int p2 = atomicAdd(g_cnt + d4.z, 1);
        int p3 = atomicAdd(g_cnt + d4.w, 1);
        if (p0 < BUCKET_CAP)
            g_bucket[(long)d4.x * BUCKET_CAP + p0] =
                ((unsigned long long)__float_as_uint(w4.x) << 32) | (unsigned)s4.x;
        if (p1 < BUCKET_CAP)
            g_bucket[(long)d4.y * BUCKET_CAP + p1] =
                ((unsigned long long)__float_as_uint(w4.y) << 32) | (unsigned)s4.y;
        if (p2 < BUCKET_CAP)
            g_bucket[(long)d4.z * BUCKET_CAP + p2] =
                ((unsigned long long)__float_as_uint(w4.z) << 32) | (unsigned)s4.z;
        if (p3 < BUCKET_CAP)
            g_bucket[(long)d4.w * BUCKET_CAP + p3] =
                ((unsigned long long)__float_as_uint(w4.w) << 32) | (unsigned)s4.w;
    } else {
        for (int e = e0; e < E; e++) {
            int d = __ldg(dst + e);
            int s = __ldg(src + e);
            unsigned w = __float_as_uint(__ldg(ew + e));
            int pos = atomicAdd(g_cnt + d, 1);
            if (pos < BUCKET_CAP)
                g_bucket[(long)d * BUCKET_CAP + pos] =
                    ((unsigned long long)w << 32) | (unsigned)s;
        }
    }
}

// ---------------------------------------------------------------------------
// Phase B: one warp per dst node. fp16 gather, fp32 accumulate, normalize.
// ---------------------------------------------------------------------------
__global__ __launch_bounds__(256) void node_aggregate(int N)
{
    int warp = (blockIdx.x * blockDim.x + threadIdx.x) >> 5;
    int lane = threadIdx.x & 31;
    if (warp >= N) return;
    int cnt = g_cnt[warp];
    if (cnt > BUCKET_CAP) cnt = BUCKET_CAP;
    const unsigned long long* bk = g_bucket + (long)warp * BUCKET_CAP;

    float4 acc = make_float4(0.f, 0.f, 0.f, 0.f);
    float wsum = 0.f;
    int e = 0;
    for (; e + 1 < cnt; e += 2) {
        unsigned long long p0 = bk[e];
        unsigned long long p1 = bk[e + 1];
        int s0 = (int)(unsigned)p0;
        int s1 = (int)(unsigned)p1;
        float w0 = __uint_as_float((unsigned)(p0 >> 32));
        float w1 = __uint_as_float((unsigned)(p1 >> 32));
        uint2 q0 = g_feat16[(long)s0 * 32 + lane];
        uint2 q1 = g_feat16[(long)s1 * 32 + lane];
        float2 a0 = u32_to_f2(q0.x);
        float2 b0 = u32_to_f2(q0.y);
        float2 a1 = u32_to_f2(q1.x);
        float2 b1 = u32_to_f2(q1.y);
        acc.x = fmaf(w0, a0.x, acc.x); acc.y = fmaf(w0, a0.y, acc.y);
        acc.z = fmaf(w0, b0.x, acc.z); acc.w = fmaf(w0, b0.y, acc.w);
        acc.x = fmaf(w1, a1.x, acc.x); acc.y = fmaf(w1, a1.y, acc.y);
        acc.z = fmaf(w1, b1.x, acc.z); acc.w = fmaf(w1, b1.y, acc.w);
        wsum += w0 + w1;
    }
    if (e < cnt) {
        unsigned long long p0 = bk[e];
        int s0 = (int)(unsigned)p0;
        float w0 = __uint_as_float((unsigned)(p0 >> 32));
        uint2 q0 = g_feat16[(long)s0 * 32 + lane];
        float2 a0 = u32_to_f2(q0.x);
        float2 b0 = u32_to_f2(q0.y);
        acc.x = fmaf(w0, a0.x, acc.x); acc.y = fmaf(w0, a0.y, acc.y);
        acc.z = fmaf(w0, b0.x, acc.z); acc.w = fmaf(w0, b0.y, acc.w);
        wsum += w0;
    }
    float inv = 1.f / (wsum + 1e-8f);
    acc.x *= inv; acc.y *= inv; acc.z *= inv; acc.w *= inv;
    *reinterpret_cast<float4*>(g_neigh + (long)warp * 128 + lane * 4) = acc;
}

// ---------------------------------------------------------------------------
// Tensor-core GEMM (3xTF32): out = relu([feat|neigh] @ B + b_self + bias)
// Block: 64 rows x 128 cols, 128 threads (4 warps). Warp w owns cols [w*32,+32).
// A tile is pre-split to tf32 hi/lo in smem (converted once per block, not per warp).
// Epilogue accumulates BN column stats. Dynamic smem (54.3 KB).
// ---------------------------------------------------------------------------
// Shared layout (floats):
//   sAhi [64][36]   @ 0      (2304)
//   sAlo [64][36]   @ 2304   (2304)
//   sBhi [32][136]  @ 4608   (4352)
//   sBlo [32][136]  @ 8960   (4352)
//   sS   [128]      @ 13312
//   sQ   [128]      @ 13440
#define SM_TOTAL_FLOATS 13568
#define sAHI(r, c) sm[(r) * 36 + (c)]
#define sALO(r, c) sm[2304 + (r) * 36 + (c)]
#define sBHI(k, n) sm[4608 + (k) * 136 + (n)]
#define sBLO(k, n) sm[8960 + (k) * 136 + (n)]
#define sSS(c) sm[13312 + (c)]
#define sQQ(c) sm[13440 + (c)]

__global__ __launch_bounds__(128) void gemm_tc(
    const float* __restrict__ feat,
    const float* __restrict__ b_self,
    const float* __restrict__ bias,
    float* __restrict__ out, int N)
{
    extern __shared__ __align__(16) float sm[];

    const int tid = threadIdx.x;
    const int warp = tid >> 5;
    const int lane = tid & 31;
    const int row0 = blockIdx.x * 64;
    const int n0w = warp * 32;
    const int lq = lane >> 2;   // 0..7
    const int lr = lane & 3;    // 0..3

    if (tid < 128) { sSS(tid) = 0.f; sQQ(tid) = 0.f; }

    float C[4][4][4];
#pragma unroll
    for (int mt = 0; mt < 4; mt++)
#pragma unroll
        for (int nt = 0; nt < 4; nt++)
#pragma unroll
            for (int j = 0; j < 4; j++) C[mt][nt][j] = 0.f;

    for (int kt = 0; kt < 8; kt++) {
        __syncthreads();
        // Load + pre-split A tile: 64 rows x 32 k (feat for kt<4, neigh for kt>=4)
        const float* Asrc = (kt < 4) ? feat : g_neigh;
        int kofs = (kt & 3) * 32;
#pragma unroll
        for (int i = 0; i < 4; i++) {
            int idx = tid + i * 128;          // 0..511 float4s
            int r = idx >> 3;
            int c4 = (idx & 7) * 4;
            float4 v = make_float4(0.f, 0.f, 0.f, 0.f);
            int gr = row0 + r;
            if (gr < N)
                v = *reinterpret_cast<const float4*>(Asrc + (long)gr * 128 + kofs + c4);
            float vv[4] = {v.x, v.y, v.z, v.w};
#pragma unroll
            for (int j = 0; j < 4; j++) {
                float hi = __uint_as_float(tf32_rna(vv[j]));
                sAHI(r, c4 + j) = hi;
                sALO(r, c4 + j) = __uint_as_float(tf32_rna(vv[j] - hi));
            }
        }
        // Load B tiles: rows kt*32 .. kt*32+31, 128 cols, hi and lo
        int kb = kt * 32;
#pragma unroll
        for (int i = 0; i < 8; i++) {
            int idx = tid + i * 128;          // 0..1023 float4s
            int kr = idx >> 5;
            int c4 = (idx & 31) * 4;
            float4 vh = *reinterpret_cast<const float4*>(g_whi + (long)(kb + kr) * 128 + c4);
            float4 vl = *reinterpret_cast<const float4*>(g_wlo + (long)(kb + kr) * 128 + c4);
            *reinterpret_cast<float4*>(&sBHI(kr, c4)) = vh;
            *reinterpret_cast<float4*>(&sBLO(kr, c4)) = vl;
        }
        __syncthreads();

#pragma unroll
        for (int k8 = 0; k8 < 4; k8++) {
            int kk = k8 * 8;
            unsigned ahi[4][4], alo[4][4];
#pragma unroll
            for (int mt = 0; mt < 4; mt++) {
                int r = mt * 16 + lq;
                ahi[mt][0] = __float_as_uint(sAHI(r, kk + lr));
                ahi[mt][1] = __float_as_uint(sAHI(r + 8, kk + lr));
                ahi[mt][2] = __float_as_uint(sAHI(r, kk + lr + 4));
                ahi[mt][3] = __float_as_uint(sAHI(r + 8, kk + lr + 4));
                alo[mt][0] = __float_as_uint(sALO(r, kk + lr));
                alo[mt][1] = __float_as_uint(sALO(r + 8, kk + lr));
                alo[mt][2] = __float_as_uint(sALO(r, kk + lr + 4));
                alo[mt][3] = __float_as_uint(sALO(r + 8, kk + lr + 4));
            }
#pragma unroll
            for (int nt = 0; nt < 4; nt++) {
                int n = n0w + nt * 8 + lq;
                unsigned bh0 = __float_as_uint(sBHI(kk + lr, n));
                unsigned bh1 = __float_as_uint(sBHI(kk + lr + 4, n));
                unsigned bl0 = __float_as_uint(sBLO(kk + lr, n));
                unsigned bl1 = __float_as_uint(sBLO(kk + lr + 4, n));
#pragma unroll
                for (int mt = 0; mt < 4; mt++) {
                    float* c = C[mt][nt];
                    asm volatile(
                        "mma.sync.aligned.m16n8k8.row.col.f32.tf32.tf32.f32 "
                        "{%0,%1,%2,%3}, {%4,%5,%6,%7}, {%8,%9}, {%0,%1,%2,%3};"
                        : "+f"(c[0]), "+f"(c[1]), "+f"(c[2]), "+f"(c[3])
                        : "r"(ahi[mt][0]), "r"(ahi[mt][1]), "r"(ahi[mt][2]), "r"(ahi[mt][3]),
                          "r"(bh0), "r"(bh1));
                    asm volatile(
                        "mma.sync.aligned.m16n8k8.row.col.f32.tf32.tf32.f32 "
                        "{%0,%1,%2,%3}, {%4,%5,%6,%7}, {%8,%9}, {%0,%1,%2,%3};"
                        : "+f"(c[0]), "+f"(c[1]), "+f"(c[2]), "+f"(c[3])
                        : "r"(ahi[mt][0]), "r"(ahi[mt][1]), "r"(ahi[mt][2]), "r"(ahi[mt][3]),
                          "r"(bl0), "r"(bl1));
                    asm volatile(
                        "mma.sync.aligned.m16n8k8.row.col.f32.tf32.tf32.f32 "
                        "{%0,%1,%2,%3}, {%4,%5,%6,%7}, {%8,%9}, {%0,%1,%2,%3};"
                        : "+f"(c[0]), "+f"(c[1]), "+f"(c[2]), "+f"(c[3])
                        : "r"(alo[mt][0]), "r"(alo[mt][1]), "r"(alo[mt][2]), "r"(alo[mt][3]),
                          "r"(bh0), "r"(bh1));
                }
            }
        }
    }

    // Epilogue: bias + ReLU, write, accumulate BN column stats.
    // C layout: c0:(r=lq, c=lr*2) c1:(r, c+1) c2:(r+8, c) c3:(r+8, c+1)
#pragma unroll
    for (int nt = 0; nt < 4; nt++) {
        int c = n0w + nt * 8 + lr * 2;
        float bc0 = __ldg(b_self + c) + __ldg(bias + c);
        float bc1 = __ldg(b_self + c + 1) + __ldg(bias + c + 1);
        float s0 = 0.f, s1 = 0.f, q0 = 0.f, q1 = 0.f;
#pragma unroll
        for (int mt = 0; mt < 4; mt++) {
            int r = row0 + mt * 16 + lq;
            if (r < N) {
                float v0 = fmaxf(C[mt][nt][0] + bc0, 0.f);
                float v1 = fmaxf(C[mt][nt][1] + bc1, 0.f);
                *reinterpret_cast<float2*>(out + (long)r * 128 + c) = make_float2(v0, v1);
                s0 += v0; s1 += v1;
                q0 = fmaf(v0, v0, q0); q1 = fmaf(v1, v1, q1);
            }
            if (r + 8 < N) {
                float v2 = fmaxf(C[mt][nt][2] + bc0, 0.f);
                float v3 = fmaxf(C[mt][nt][3] + bc1, 0.f);
                *reinterpret_cast<float2*>(out + (long)(r + 8) * 128 + c) = make_float2(v2, v3);
                s0 += v2; s1 += v3;
                q0 = fmaf(v2, v2, q0); q1 = fmaf(v3, v3, q1);
            }
        }
        atomicAdd(&sSS(c), s0); atomicAdd(&sSS(c + 1), s1);
        atomicAdd(&sQQ(c), q0); atomicAdd(&sQQ(c + 1), q1);
    }
    __syncthreads();
    if (tid < 128) {
        atomicAdd(g_colsum + tid, sSS(tid));
        atomicAdd(g_colsq + tid, sQQ(tid));
    }
}

// ---------------------------------------------------------------------------
// BatchNorm apply (finalize folded in: every block recomputes scale/shift
// from the completed global sums — deterministic, race-free)
// ---------------------------------------------------------------------------
__global__ __launch_bounds__(256) void bn_apply(
    float* __restrict__ out,
    const float* __restrict__ gamma, const float* __restrict__ beta,
    float invN, long tot4)
{
    __shared__ float sc[128];
    __shared__ float sh[128];
    int tid = threadIdx.x;
    if (tid < 128) {
        float mu = g_colsum[tid] * invN;
        float var = g_colsq[tid] * invN - mu * mu;
        float s = rsqrtf(var + 1e-5f) * gamma[tid];
        sc[tid] = s;
        sh[tid] = beta[tid] - mu * s;
    }
    __syncthreads();
    long i = (long)blockIdx.x * blockDim.x + tid;
    if (i >= tot4) return;
    float4 v = reinterpret_cast<float4*>(out)[i];
    int c0 = (int)(i & 31) * 4;
    v.x = v.x * sc[c0 + 0] + sh[c0 + 0];
    v.y = v.y * sc[c0 + 1] + sh[c0 + 1];
    v.z = v.z * sc[c0 + 2] + sh[c0 + 2];
    v.w = v.w * sc[c0 + 3] + sh[c0 + 3];
    reinterpret_cast<float4*>(out)[i] = v;
}

// ---------------------------------------------------------------------------
extern "C" void kernel_launch(void* const* d_in, const int* in_sizes, int n_in,
                              void* d_out, int out_size) {
    const float* feat   = (const float*)d_in[0];
    const int*   src    = (const int*)  d_in[1];
    const int*   dst    = (const int*)  d_in[2];
    const float* ew     = (const float*)d_in[3];
    const float* Wn     = (const float*)d_in[4];
    const float* Ws     = (const float*)d_in[5];
    const float* b_self = (const float*)d_in[6];
    const float* bias   = (const float*)d_in[7];
    const float* gamma  = (const float*)d_in[8];
    const float* beta   = (const float*)d_in[9];
    float* out = (float*)d_out;

    int N = in_sizes[0] / 128;
    int E = in_sizes[1];
    long tot4 = (long)N * 32;
    int smem_bytes = SM_TOTAL_FLOATS * 4;

    cudaFuncSetAttribute(gemm_tc, cudaFuncAttributeMaxDynamicSharedMemorySize, smem_bytes);

    prep<<<(int)((tot4 + 255) / 256), 256>>>(feat, Wn, Ws, N, tot4);
    edge_bin<<<(E / 4 + 255) / 256, 256>>>(src, dst, ew, E);
    node_aggregate<<<(N + 7) / 8, 256>>>(N);
    gemm_tc<<<(N + 63) / 64, 128, smem_bytes>>>(feat, b_self, bias, out, N);
    bn_apply<<<(int)((tot4 + 255) / 256), 256>>>(out, gamma, beta, 1.0f / (float)N, tot4);
}

// round 11
// speedup vs baseline: 1.3240x; 1.2248x over previous
#include <cuda_runtime.h>
#include <cuda_fp16.h>
#include <cstdint>

#define NODES_CAP 50000
#define BUCKET_CAP 64

// Scratch (no allocations allowed -> __device__ globals)
__device__ uint2 g_feat16[(size_t)NODES_CAP * 32];   // feat fp16 hi, row-major [N][128]
__device__ uint2 g_featlo[(size_t)NODES_CAP * 32];   // feat fp16 lo residual
__device__ uint2 g_nhi[(size_t)NODES_CAP * 32];      // neigh fp16 hi
__device__ uint2 g_nlo[(size_t)NODES_CAP * 32];      // neigh fp16 lo
__device__ int g_cnt[NODES_CAP];
__device__ unsigned long long g_bucket[(size_t)NODES_CAP * BUCKET_CAP];  // (w<<32)|src
__device__ __half g_wh[128 * 256];   // combined W^T, n-major [n][k], fp16 hi
__device__ __half g_wl[128 * 256];   // fp16 lo residual
__device__ float g_colsum[128];
__device__ float g_colsq[128];

__device__ __forceinline__ unsigned h2_to_u32(__half2 h) {
    union { __half2 h; unsigned u; } cv;
    cv.h = h;
    return cv.u;
}

__device__ __forceinline__ float2 u32_to_f2(unsigned u) {
    union { unsigned u; __half2 h; } cv;
    cv.u = u;
    return __half22float2(cv.h);
}

__device__ __forceinline__ void split_f16(float v, __half& hi, __half& lo) {
    hi = __float2half_rn(v);
    lo = __float2half_rn(v - __half2float(hi));
}

// ---------------------------------------------------------------------------
// Prep (fused): zero counters/stats + feat->fp16 hi/lo + weight fp16 split
// ---------------------------------------------------------------------------
__global__ __launch_bounds__(256) void prep(
    const float* __restrict__ feat,
    const float* __restrict__ Wn, const float* __restrict__ Ws,
    int N, long tot4)
{
    long i = (long)blockIdx.x * blockDim.x + threadIdx.x;
    if (i < tot4) {
        float4 v = reinterpret_cast<const float4*>(feat)[i];
        __half h0, h1, h2, h3, l0, l1, l2, l3;
        split_f16(v.x, h0, l0); split_f16(v.y, h1, l1);
        split_f16(v.z, h2, l2); split_f16(v.w, h3, l3);
        uint2 ph, pl;
        ph.x = h2_to_u32(__halves2half2(h0, h1));
        ph.y = h2_to_u32(__halves2half2(h2, h3));
        pl.x = h2_to_u32(__halves2half2(l0, l1));
        pl.y = h2_to_u32(__halves2half2(l2, l3));
        g_feat16[i] = ph;
        g_featlo[i] = pl;
    }
    if (i < N) g_cnt[i] = 0;
    if (i < 128) { g_colsum[i] = 0.f; g_colsq[i] = 0.f; }
    if (i < 128 * 256) {
        int n = (int)i >> 8, k = (int)i & 255;
        float v = (k < 128) ? Ws[n * 128 + k] : Wn[n * 128 + (k - 128)];
        __half hi, lo;
        split_f16(v, hi, lo);
        g_wh[i] = hi;
        g_wl[i] = lo;
    }
}

// ---------------------------------------------------------------------------
// Phase A: bin edges into per-dst buckets. 4 edges per thread (ILP).
// ---------------------------------------------------------------------------
__global__ __launch_bounds__(256) void edge_bin(
    const int* __restrict__ src, const int* __restrict__ dst,
    const float* __restrict__ ew, int E)
{
    int t = blockIdx.x * blockDim.x + threadIdx.x;
    int e0 = t * 4;
    if (e0 >= E) return;
    if (e0 + 3 < E) {
        int4 s4 = *reinterpret_cast<const int4*>(src + e0);
        int4 d4 = *reinterpret_cast<const int4*>(dst + e0);
        float4 w4 = *reinterpret_cast<const float4*>(ew + e0);
        int p0 = atomicAdd(g_cnt + d4.x, 1);
        int p1 = atomicAdd(g_cnt + d4.y, 1);
        int p2 = atomicAdd(g_cnt + d4.z, 1);
        int p3 = atomicAdd(g_cnt + d4.w, 1);
        if (p0 < BUCKET_CAP)
            g_bucket[(long)d4.x * BUCKET_CAP + p0] =
                ((unsigned long long)__float_as_uint(w4.x) << 32) | (unsigned)s4.x;
        if (p1 < BUCKET_CAP)
            g_bucket[(long)d4.y * BUCKET_CAP + p1] =
                ((unsigned long long)__float_as_uint(w4.y) << 32) | (unsigned)s4.y;
        if (p2 < BUCKET_CAP)
            g_bucket[(long)d4.z * BUCKET_CAP + p2] =
                ((unsigned long long)__float_as_uint(w4.z) << 32) | (unsigned)s4.z;
        if (p3 < BUCKET_CAP)
            g_bucket[(long)d4.w * BUCKET_CAP + p3] =
                ((unsigned long long)__float_as_uint(w4.w) << 32) | (unsigned)s4.w;
    } else {
        for (int e = e0; e < E; e++) {
            int d = __ldg(dst + e);
            int s = __ldg(src + e);
            unsigned w = __float_as_uint(__ldg(ew + e));
            int pos = atomicAdd(g_cnt + d, 1);
            if (pos < BUCKET_CAP)
                g_bucket[(long)d * BUCKET_CAP + pos] =
                    ((unsigned long long)w << 32) | (unsigned)s;
        }
    }
}

// ---------------------------------------------------------------------------
// Phase B: one warp per dst. fp16 gather, fp32 accumulate, normalize, write
// neigh as fp16 hi/lo.
// ---------------------------------------------------------------------------
__global__ __launch_bounds__(256) void node_aggregate(int N)
{
    int warp = (blockIdx.x * blockDim.x + threadIdx.x) >> 5;
    int lane = threadIdx.x & 31;
    if (warp >= N) return;
    int cnt = g_cnt[warp];
    if (cnt > BUCKET_CAP) cnt = BUCKET_CAP;
    const unsigned long long* bk = g_bucket + (long)warp * BUCKET_CAP;

    float4 acc = make_float4(0.f, 0.f, 0.f, 0.f);
    float wsum = 0.f;
    int e = 0;
    for (; e + 1 < cnt; e += 2) {
        unsigned long long p0 = bk[e];
        unsigned long long p1 = bk[e + 1];
        int s0 = (int)(unsigned)p0;
        int s1 = (int)(unsigned)p1;
        float w0 = __uint_as_float((unsigned)(p0 >> 32));
        float w1 = __uint_as_float((unsigned)(p1 >> 32));
        uint2 q0 = g_feat16[(long)s0 * 32 + lane];
        uint2 q1 = g_feat16[(long)s1 * 32 + lane];
        float2 a0 = u32_to_f2(q0.x);
        float2 b0 = u32_to_f2(q0.y);
        float2 a1 = u32_to_f2(q1.x);
        float2 b1 = u32_to_f2(q1.y);
        acc.x = fmaf(w0, a0.x, acc.x); acc.y = fmaf(w0, a0.y, acc.y);
        acc.z = fmaf(w0, b0.x, acc.z); acc.w = fmaf(w0, b0.y, acc.w);
        acc.x = fmaf(w1, a1.x, acc.x); acc.y = fmaf(w1, a1.y, acc.y);
        acc.z = fmaf(w1, b1.x, acc.z); acc.w = fmaf(w1, b1.y, acc.w);
        wsum += w0 + w1;
    }
    if (e < cnt) {
        unsigned long long p0 = bk[e];
        int s0 = (int)(unsigned)p0;
        float w0 = __uint_as_float((unsigned)(p0 >> 32));
        uint2 q0 = g_feat16[(long)s0 * 32 + lane];
        float2 a0 = u32_to_f2(q0.x);
        float2 b0 = u32_to_f2(q0.y);
        acc.x = fmaf(w0, a0.x, acc.x); acc.y = fmaf(w0, a0.y, acc.y);
        acc.z = fmaf(w0, b0.x, acc.z); acc.w = fmaf(w0, b0.y, acc.w);
        wsum += w0;
    }
    float inv = 1.f / (wsum + 1e-8f);
    acc.x *= inv; acc.y *= inv; acc.z *= inv; acc.w *= inv;
    __half h0, h1, h2, h3, l0, l1, l2, l3;
    split_f16(acc.x, h0, l0); split_f16(acc.y, h1, l1);
    split_f16(acc.z, h2, l2); split_f16(acc.w, h3, l3);
    uint2 ph, pl;
    ph.x = h2_to_u32(__halves2half2(h0, h1));
    ph.y = h2_to_u32(__halves2half2(h2, h3));
    pl.x = h2_to_u32(__halves2half2(l0, l1));
    pl.y = h2_to_u32(__halves2half2(l2, l3));
    g_nhi[(long)warp * 32 + lane] = ph;
    g_nlo[(long)warp * 32 + lane] = pl;
}

// ---------------------------------------------------------------------------
// Tensor-core GEMM (3xFP16 m16n8k16): out = relu([feat|neigh] @ B + biases)
// Block: 64 rows x 128 cols, 128 threads (4 warps); warp w owns cols [w*32,+32).
// A/B pre-split to fp16 hi/lo in gmem; K tile = 64 (4 tiles over K=256).
// Smem pitch 72 halves (36 words) -> conflict-free fragment LDS.
// Epilogue accumulates BN column stats. Dynamic smem 56320 B.
// ---------------------------------------------------------------------------
// word-offsets (uint32 units): AHI 0 (64x36), ALO 2304, BHI 4608 (128x36),
// BLO 9216; float stats: sS @word 13824, sQ @word 13952. Total 14080 words.
#define W_AHI 0
#define W_ALO 2304
#define W_BHI 4608
#define W_BLO 9216
#define W_SS 13824
#define W_SQ 13952
#define SMEM_BYTES (14080 * 4)

__global__ __launch_bounds__(128) void gemm_tc(
    const float* __restrict__ b_self,
    const float* __restrict__ bias,
    float* __restrict__ out, int N)
{
    extern __shared__ __align__(16) unsigned smw[];
    float* smf = reinterpret_cast<float*>(smw);

    const int tid = threadIdx.x;
    const int warp = tid >> 5;
    const int lane = tid & 31;
    const int row0 = blockIdx.x * 64;
    const int n0w = warp * 32;
    const int lq = lane >> 2;   // 0..7
    const int lr = lane & 3;    // 0..3

    if (tid < 128) { smf[W_SS + tid] = 0.f; smf[W_SQ + tid] = 0.f; }

    float C[4][4][4];
#pragma unroll
    for (int mt = 0; mt < 4; mt++)
#pragma unroll
        for (int nt = 0; nt < 4; nt++)
#pragma unroll
            for (int j = 0; j < 4; j++) C[mt][nt][j] = 0.f;

    for (int kt = 0; kt < 4; kt++) {
        __syncthreads();
        // A tile: 64 rows x 64 k fp16 (hi+lo). Source: feat (kt<2) or neigh.
        const uint4* AH = (kt < 2) ? reinterpret_cast<const uint4*>(g_feat16)
                                   : reinterpret_cast<const uint4*>(g_nhi);
        const uint4* AL = (kt < 2) ? reinterpret_cast<const uint4*>(g_featlo)
                                   : reinterpret_cast<const uint4*>(g_nlo);
        int kofs8 = (kt & 1) * 8;   // uint4 offset within row (8 halves each)
#pragma unroll
        for (int i = 0; i < 4; i++) {
            int idx = tid + i * 128;      // 0..511
            int r = idx >> 3;
            int c8 = idx & 7;
            uint4 vh = make_uint4(0, 0, 0, 0), vl = vh;
            int gr = row0 + r;
            if (gr < N) {
                vh = AH[gr * 16 + kofs8 + c8];
                vl = AL[gr * 16 + kofs8 + c8];
            }
            // half-offset r*72 + c8*8 -> word offset r*36 + c8*4 (16B aligned)
            *reinterpret_cast<uint4*>(smw + W_AHI + r * 36 + c8 * 4) = vh;
            *reinterpret_cast<uint4*>(smw + W_ALO + r * 36 + c8 * 4) = vl;
        }
        // B tile: 128 n x 64 k fp16 (hi+lo), n-major gmem [n][256]
        int kb8 = kt * 8;
#pragma unroll
        for (int i = 0; i < 8; i++) {
            int idx = tid + i * 128;      // 0..1023
            int n = idx >> 3;
            int c8 = idx & 7;
            uint4 vh = reinterpret_cast<const uint4*>(g_wh)[n * 32 + kb8 + c8];
            uint4 vl = reinterpret_cast<const uint4*>(g_wl)[n * 32 + kb8 + c8];
            *reinterpret_cast<uint4*>(smw + W_BHI + n * 36 + c8 * 4) = vh;
            *reinterpret_cast<uint4*>(smw + W_BLO + n * 36 + c8 * 4) = vl;
        }
        __syncthreads();

#pragma unroll
        for (int k16 = 0; k16 < 4; k16++) {
            int kb = k16 * 8;   // word base within row
            unsigned ah[4][4], al[4][4];
#pragma unroll
            for (int mt = 0; mt < 4; mt++) {
                int r = mt * 16 + lq;
                ah[mt][0] = smw[W_AHI + r * 36 + kb + lr];
                ah[mt][1] = smw[W_AHI + (r + 8) * 36 + kb + lr];
                ah[mt][2] = smw[W_AHI + r * 36 + kb + 4 + lr];
                ah[mt][3] = smw[W_AHI + (r + 8) * 36 + kb + 4 + lr];
                al[mt][0] = smw[W_ALO + r * 36 + kb + lr];
                al[mt][1] = smw[W_ALO + (r + 8) * 36 + kb + lr];
                al[mt][2] = smw[W_ALO + r * 36 + kb + 4 + lr];
                al[mt][3] = smw[W_ALO + (r + 8) * 36 + kb + 4 + lr];
            }
#pragma unroll
            for (int nt = 0; nt < 4; nt++) {
                int n = n0w + nt * 8 + lq;
                unsigned bh0 = smw[W_BHI + n * 36 + kb + lr];
                unsigned bh1 = smw[W_BHI + n * 36 + kb + 4 + lr];
                unsigned bl0 = smw[W_BLO + n * 36 + kb + lr];
                unsigned bl1 = smw[W_BLO + n * 36 + kb + 4 + lr];
#pragma unroll
                for (int mt = 0; mt < 4; mt++) {
                    float* c = C[mt][nt];
                    asm volatile(
                        "mma.sync.aligned.m16n8k16.row.col.f32.f16.f16.f32 "
                        "{%0,%1,%2,%3}, {%4,%5,%6,%7}, {%8,%9}, {%0,%1,%2,%3};"
                        : "+f"(c[0]), "+f"(c[1]), "+f"(c[2]), "+f"(c[3])
                        : "r"(ah[mt][0]), "r"(ah[mt][1]), "r"(ah[mt][2]), "r"(ah[mt][3]),
                          "r"(bh0), "r"(bh1));
                    asm volatile(
                        "mma.sync.aligned.m16n8k16.row.col.f32.f16.f16.f32 "
                        "{%0,%1,%2,%3}, {%4,%5,%6,%7}, {%8,%9}, {%0,%1,%2,%3};"
                        : "+f"(c[0]), "+f"(c[1]), "+f"(c[2]), "+f"(c[3])
                        : "r"(ah[mt][0]), "r"(ah[mt][1]), "r"(ah[mt][2]), "r"(ah[mt][3]),
                          "r"(bl0), "r"(bl1));
                    asm volatile(
                        "mma.sync.aligned.m16n8k16.row.col.f32.f16.f16.f32 "
                        "{%0,%1,%2,%3}, {%4,%5,%6,%7}, {%8,%9}, {%0,%1,%2,%3};"
                        : "+f"(c[0]), "+f"(c[1]), "+f"(c[2]), "+f"(c[3])
                        : "r"(al[mt][0]), "r"(al[mt][1]), "r"(al[mt][2]), "r"(al[mt][3]),
                          "r"(bh0), "r"(bh1));
                }
            }
        }
    }

    // Epilogue: bias + ReLU, write, accumulate BN column stats.
    // C layout: c0:(r=lq, c=lr*2) c1:(r, c+1) c2:(r+8, c) c3:(r+8, c+1)
#pragma unroll
    for (int nt = 0; nt < 4; nt++) {
        int c = n0w + nt * 8 + lr * 2;
        float bc0 = __ldg(b_self + c) + __ldg(bias + c);
        float bc1 = __ldg(b_self + c + 1) + __ldg(bias + c + 1);
        float s0 = 0.f, s1 = 0.f, q0 = 0.f, q1 = 0.f;
#pragma unroll
        for (int mt = 0; mt < 4; mt++) {
            int r = row0 + mt * 16 + lq;
            if (r < N) {
                float v0 = fmaxf(C[mt][nt][0] + bc0, 0.f);
                float v1 = fmaxf(C[mt][nt][1] + bc1, 0.f);
                *reinterpret_cast<float2*>(out + (long)r * 128 + c) = make_float2(v0, v1);
                s0 += v0; s1 += v1;
                q0 = fmaf(v0, v0, q0); q1 = fmaf(v1, v1, q1);
            }
            if (r + 8 < N) {
                float v2 = fmaxf(C[mt][nt][2] + bc0, 0.f);
                float v3 = fmaxf(C[mt][nt][3] + bc1, 0.f);
                *reinterpret_cast<float2*>(out + (long)(r + 8) * 128 + c) = make_float2(v2, v3);
                s0 += v2; s1 += v3;
                q0 = fmaf(v2, v2, q0); q1 = fmaf(v3, v3, q1);
            }
        }
        atomicAdd(&smf[W_SS + c], s0); atomicAdd(&smf[W_SS + c + 1], s1);
        atomicAdd(&smf[W_SQ + c], q0); atomicAdd(&smf[W_SQ + c + 1], q1);
    }
    __syncthreads();
    if (tid < 128) {
        atomicAdd(g_colsum + tid, smf[W_SS + tid]);
        atomicAdd(g_colsq + tid, smf[W_SQ + tid]);
    }
}

// ---------------------------------------------------------------------------
// BatchNorm apply (finalize folded in; every block recomputes scale/shift)
// ---------------------------------------------------------------------------
__global__ __launch_bounds__(256) void bn_apply(
    float* __restrict__ out,
    const float* __restrict__ gamma, const float* __restrict__ beta,
    float invN, long tot4)
{
    __shared__ float sc[128];
    __shared__ float sh[128];
    int tid = threadIdx.x;
    if (tid < 128) {
        float mu = g_colsum[tid] * invN;
        float var = g_colsq[tid] * invN - mu * mu;
        float s = rsqrtf(var + 1e-5f) * gamma[tid];
        sc[tid] = s;
        sh[tid] = beta[tid] - mu * s;
    }
    __syncthreads();
    long i = (long)blockIdx.x * blockDim.x + tid;
    if (i >= tot4) return;
    float4 v = reinterpret_cast<float4*>(out)[i];
    int c0 = (int)(i & 31) * 4;
    v.x = v.x * sc[c0 + 0] + sh[c0 + 0];
    v.y = v.y * sc[c0 + 1] + sh[c0 + 1];
    v.z = v.z * sc[c0 + 2] + sh[c0 + 2];
    v.w = v.w * sc[c0 + 3] + sh[c0 + 3];
    reinterpret_cast<float4*>(out)[i] = v;
}

// ---------------------------------------------------------------------------
extern "C" void kernel_launch(void* const* d_in, const int* in_sizes, int n_in,
                              void* d_out, int out_size) {
    const float* feat   = (const float*)d_in[0];
    const int*   src    = (const int*)  d_in[1];
    const int*   dst    = (const int*)  d_in[2];
    const float* ew     = (const float*)d_in[3];
    const float* Wn     = (const float*)d_in[4];
    const float* Ws     = (const float*)d_in[5];
    const float* b_self = (const float*)d_in[6];
    const float* bias   = (const float*)d_in[7];
    const float* gamma  = (const float*)d_in[8];
    const float* beta   = (const float*)d_in[9];
    float* out = (float*)d_out;

    int N = in_sizes[0] / 128;
    int E = in_sizes[1];
    long tot4 = (long)N * 32;

    cudaFuncSetAttribute(gemm_tc, cudaFuncAttributeMaxDynamicSharedMemorySize, SMEM_BYTES);

    prep<<<(int)((tot4 + 255) / 256), 256>>>(feat, Wn, Ws, N, tot4);
    edge_bin<<<(E / 4 + 255) / 256, 256>>>(src, dst, ew, E);
    node_aggregate<<<(N + 7) / 8, 256>>>(N);
    gemm_tc<<<(N + 63) / 64, 128, SMEM_BYTES>>>(b_self, bias, out, N);
    bn_apply<<<(int)((tot4 + 255) / 256), 256>>>(out, gamma, beta, 1.0f / (float)N, tot4);
}